// round 1
// baseline (speedup 1.0000x reference)
#include <cuda_runtime.h>
#include <cstdint>
#include <math.h>

#define T_STEPS 256
#define B_DIM   128
#define D_DIM   1024
#define BD      (B_DIM * D_DIM)          // 131072
#define M_TOT   (T_STEPS * B_DIM)        // 32768

// ---------------- scratch (device globals; no cudaMalloc allowed) ----------
__device__ float g_Z[T_STEPS * (size_t)BD];      // gated pre-activations, 134 MB
__device__ float g_Xr[T_STEPS * (size_t)BD];     // tf32-rounded xs, 134 MB
__device__ float g_Wr[D_DIM * D_DIM];            // tf32-rounded W, 4 MB
__device__ float g_colsum[T_STEPS * D_DIM];      // sum over b of xs[t,:,d]
__device__ float g_wcol[D_DIM];                  // sum over e of W[e,d]
__device__ float g_sign[T_STEPS];                // gate sign per step

// ---------------- helpers ---------------------------------------------------
__device__ __forceinline__ float tf32_rna(float x) {
    uint32_t u;
    asm("cvt.rna.tf32.f32 %0, %1;" : "=r"(u) : "f"(x));
    return __uint_as_float(u);
}

__device__ __forceinline__ void cp_async16(void* smem, const void* gmem) {
    uint32_t s = (uint32_t)__cvta_generic_to_shared(smem);
    asm volatile("cp.async.ca.shared.global [%0], [%1], 16;\n" :: "r"(s), "l"(gmem));
}
#define CP_COMMIT() asm volatile("cp.async.commit_group;\n" ::: "memory")

__device__ __forceinline__ void mma_tf32(float4& d, const uint32_t a[4],
                                         uint32_t b0, uint32_t b1) {
    asm volatile(
        "mma.sync.aligned.m16n8k8.row.col.f32.tf32.tf32.f32 "
        "{%0,%1,%2,%3}, {%4,%5,%6,%7}, {%8,%9}, {%0,%1,%2,%3};"
        : "+f"(d.x), "+f"(d.y), "+f"(d.z), "+f"(d.w)
        : "r"(a[0]), "r"(a[1]), "r"(a[2]), "r"(a[3]), "r"(b0), "r"(b1));
}

// ---------------- kernel 1: column sums of xs over b + tf32 pre-round -------
// grid (D/256, T), block 256. Reads xs once, writes rounded copy + colsum.
__global__ void colsum_cvt_kernel(const float* __restrict__ xs) {
    int d = blockIdx.x * 256 + threadIdx.x;
    int t = blockIdx.y;
    const float* base = xs + (size_t)t * BD + d;
    float*       outb = g_Xr + (size_t)t * BD + d;
    float s = 0.f;
#pragma unroll 8
    for (int b = 0; b < B_DIM; b++) {
        float v = base[(size_t)b * D_DIM];
        s += v;
        outb[(size_t)b * D_DIM] = tf32_rna(v);
    }
    g_colsum[t * D_DIM + d] = s;
}

// ---------------- kernel 2: column sums of W over e + tf32 pre-round --------
// grid (D/256), block 256.
__global__ void wcol_cvt_kernel(const float* __restrict__ W) {
    int d = blockIdx.x * 256 + threadIdx.x;
    float s = 0.f;
#pragma unroll 8
    for (int e = 0; e < D_DIM; e++) {
        float v = W[(size_t)e * D_DIM + d];
        s += v;
        g_Wr[(size_t)e * D_DIM + d] = tf32_rna(v);
    }
    g_wcol[d] = s;
}

// ---------------- kernel 3: gate sign per timestep ---------------------------
// sum_{b,e} z[t] = dot(colsum_x[t,:], wcol) + B * sum(bias)
// grid (T), block 256.
__global__ void gate_kernel(const float* __restrict__ bias) {
    int t = blockIdx.x;
    int tid = threadIdx.x;
    float p = 0.f;
    for (int d = tid; d < D_DIM; d += 256) {
        p += g_colsum[t * D_DIM + d] * g_wcol[d] + 128.0f * bias[d];
    }
    __shared__ float red[256];
    red[tid] = p;
    __syncthreads();
    for (int s = 128; s > 0; s >>= 1) {
        if (tid < s) red[tid] += red[tid + s];
        __syncthreads();
    }
    if (tid == 0) g_sign[t] = (red[0] > 0.f) ? 1.f : -1.f;
}

// ---------------- kernel 4: Z = sign[t] * (xs @ W^T + b), TF32 GEMM ----------
// M=32768 (rows = t*B+b), N=1024, K=1024. 64x64x32 CTA tile, 4 warps (32x32
// warp tiles), mma.sync m16n8k8 tf32, cp.async double buffer. Static smem 36KB.
__global__ void __launch_bounds__(128) gemm_kernel(const float* __restrict__ bias) {
    __shared__ float sA[2][64][36];
    __shared__ float sB[2][64][36];

    const int tid  = threadIdx.x;
    const int lane = tid & 31;
    const int warp = tid >> 5;       // 0..3
    const int wm   = warp >> 1;      // m sub-tile: 0..1 (each 32 rows)
    const int wn   = warp & 1;       // n sub-tile: 0..1 (each 32 cols)
    const int lr   = lane >> 2;      // 0..7
    const int lc   = lane & 3;       // 0..3

    const int bx = blockIdx.x;       // n tile  (N/64 = 16)
    const int by = blockIdx.y;       // m tile  (M/64 = 512)

    const float* Ag = g_Xr + (size_t)by * 64 * D_DIM;
    const float* Bg = g_Wr + (size_t)bx * 64 * D_DIM;

    const int ldr = tid >> 3;        // loader row 0..15
    const int ldv = tid & 7;         // loader vec4 col 0..7

    float4 acc[2][4];
#pragma unroll
    for (int i = 0; i < 2; i++)
#pragma unroll
        for (int j = 0; j < 4; j++) acc[i][j] = make_float4(0.f, 0.f, 0.f, 0.f);

    auto load_stage = [&](int buf, int kt) {
        const float* ag = Ag + kt * 32 + ldv * 4;
        const float* bg = Bg + kt * 32 + ldv * 4;
#pragma unroll
        for (int rr = 0; rr < 4; rr++) {
            int r = ldr + rr * 16;
            cp_async16(&sA[buf][r][ldv * 4], ag + (size_t)r * D_DIM);
            cp_async16(&sB[buf][r][ldv * 4], bg + (size_t)r * D_DIM);
        }
        CP_COMMIT();
    };

    load_stage(0, 0);

    const int NT = D_DIM / 32;  // 32 k-tiles
    for (int kt = 0; kt < NT; kt++) {
        int cur = kt & 1;
        if (kt + 1 < NT) {
            load_stage(cur ^ 1, kt + 1);
            asm volatile("cp.async.wait_group 1;\n" ::: "memory");
        } else {
            asm volatile("cp.async.wait_group 0;\n" ::: "memory");
        }
        __syncthreads();

#pragma unroll
        for (int s = 0; s < 4; s++) {
            const int c0 = s * 8 + lc;
            uint32_t af[2][4];
#pragma unroll
            for (int i = 0; i < 2; i++) {
                int r0 = wm * 32 + i * 16 + lr;
                af[i][0] = __float_as_uint(sA[cur][r0][c0]);
                af[i][1] = __float_as_uint(sA[cur][r0 + 8][c0]);
                af[i][2] = __float_as_uint(sA[cur][r0][c0 + 4]);
                af[i][3] = __float_as_uint(sA[cur][r0 + 8][c0 + 4]);
            }
#pragma unroll
            for (int j = 0; j < 4; j++) {
                int n0 = wn * 32 + j * 8 + lr;
                uint32_t b0 = __float_as_uint(sB[cur][n0][c0]);
                uint32_t b1 = __float_as_uint(sB[cur][n0][c0 + 4]);
#pragma unroll
                for (int i = 0; i < 2; i++) mma_tf32(acc[i][j], af[i], b0, b1);
            }
        }
        __syncthreads();
    }

    // epilogue: gate sign is uniform per CTA row-tile (64 | 128, t = by/2)
    const float sgn = g_sign[by >> 1];
#pragma unroll
    for (int i = 0; i < 2; i++) {
        int row = by * 64 + wm * 32 + i * 16 + lr;
#pragma unroll
        for (int j = 0; j < 4; j++) {
            int col = bx * 64 + wn * 32 + j * 8 + lc * 2;
            float bc0 = bias[col], bc1 = bias[col + 1];
            float2 v0 = make_float2(sgn * (acc[i][j].x + bc0), sgn * (acc[i][j].y + bc1));
            float2 v1 = make_float2(sgn * (acc[i][j].z + bc0), sgn * (acc[i][j].w + bc1));
            *reinterpret_cast<float2*>(&g_Z[(size_t)row * D_DIM + col])       = v0;
            *reinterpret_cast<float2*>(&g_Z[(size_t)(row + 8) * D_DIM + col]) = v1;
        }
    }
}

// ---------------- kernel 5: elementwise scan h = tanh(Z[t] + h) --------------
// grid (BD/256), block 256. Each thread owns one (b,d) element.
__global__ void scan_kernel(float* __restrict__ out, int out_size) {
    int gid = blockIdx.x * 256 + threadIdx.x;   // 0 .. BD-1
    float h = 0.f;
#pragma unroll 4
    for (int t = 0; t < T_STEPS; t++) {
        h = tanhf(g_Z[(size_t)t * BD + gid] + h);
    }
    out[gid] = h;
    if (out_size >= 2 * BD) out[BD + gid] = h;   // reference returns (h, h)
}

// ---------------- launch -----------------------------------------------------
extern "C" void kernel_launch(void* const* d_in, const int* in_sizes, int n_in,
                              void* d_out, int out_size) {
    const float* xs   = (const float*)d_in[0];   // [T, B, D]
    const float* W    = (const float*)d_in[1];   // [D, D]
    const float* bias = (const float*)d_in[2];   // [D]
    float* out = (float*)d_out;

    colsum_cvt_kernel<<<dim3(D_DIM / 256, T_STEPS), 256>>>(xs);
    wcol_cvt_kernel<<<D_DIM / 256, 256>>>(W);
    gate_kernel<<<T_STEPS, 256>>>(bias);
    gemm_kernel<<<dim3(D_DIM / 64, M_TOT / 64), 128>>>(bias);
    scan_kernel<<<BD / 256, 256>>>(out, out_size);
}

// round 3
// speedup vs baseline: 1.1860x; 1.1860x over previous
#include <cuda_runtime.h>
#include <cstdint>
#include <math.h>

#define T_STEPS 256
#define B_DIM   128
#define D_DIM   1024
#define BD      (B_DIM * D_DIM)          // 131072
#define M_TOT   (T_STEPS * B_DIM)        // 32768

// ---------------- scratch (device globals; no cudaMalloc allowed) ----------
__device__ float g_Z[T_STEPS * (size_t)BD];      // gated pre-activations, 134 MB
__device__ float g_Xr[T_STEPS * (size_t)BD];     // tf32-rounded xs, 134 MB
__device__ float g_Wr[D_DIM * D_DIM];            // tf32-rounded W, 4 MB
__device__ float g_colsum[T_STEPS * D_DIM];      // sum over b of xs[t,:,d]
__device__ float g_wcol[D_DIM];                  // sum over e of W[e,d]
__device__ float g_sign[T_STEPS];                // gate sign per step

// ---------------- helpers ---------------------------------------------------
__device__ __forceinline__ float tf32_rna(float x) {
    uint32_t u;
    asm("cvt.rna.tf32.f32 %0, %1;" : "=r"(u) : "f"(x));
    return __uint_as_float(u);
}

__device__ __forceinline__ void cp_async16(void* smem, const void* gmem) {
    uint32_t s = (uint32_t)__cvta_generic_to_shared(smem);
    asm volatile("cp.async.cg.shared.global [%0], [%1], 16;\n" :: "r"(s), "l"(gmem));
}
#define CP_COMMIT() asm volatile("cp.async.commit_group;\n" ::: "memory")

__device__ __forceinline__ void mma_tf32(float4& d, const uint32_t a[4],
                                         uint32_t b0, uint32_t b1) {
    asm volatile(
        "mma.sync.aligned.m16n8k8.row.col.f32.tf32.tf32.f32 "
        "{%0,%1,%2,%3}, {%4,%5,%6,%7}, {%8,%9}, {%0,%1,%2,%3};"
        : "+f"(d.x), "+f"(d.y), "+f"(d.z), "+f"(d.w)
        : "r"(a[0]), "r"(a[1]), "r"(a[2]), "r"(a[3]), "r"(b0), "r"(b1));
}

// ---------------- kernel 1: column sums of xs over b + tf32 pre-round -------
__global__ void colsum_cvt_kernel(const float* __restrict__ xs) {
    int d = blockIdx.x * 256 + threadIdx.x;
    int t = blockIdx.y;
    const float* base = xs + (size_t)t * BD + d;
    float*       outb = g_Xr + (size_t)t * BD + d;
    float s = 0.f;
#pragma unroll 8
    for (int b = 0; b < B_DIM; b++) {
        float v = base[(size_t)b * D_DIM];
        s += v;
        outb[(size_t)b * D_DIM] = tf32_rna(v);
    }
    g_colsum[t * D_DIM + d] = s;
}

// ---------------- kernel 2: column sums of W over e + tf32 pre-round --------
__global__ void wcol_cvt_kernel(const float* __restrict__ W) {
    int d = blockIdx.x * 256 + threadIdx.x;
    float s = 0.f;
#pragma unroll 8
    for (int e = 0; e < D_DIM; e++) {
        float v = W[(size_t)e * D_DIM + d];
        s += v;
        g_Wr[(size_t)e * D_DIM + d] = tf32_rna(v);
    }
    g_wcol[d] = s;
}

// ---------------- kernel 3: gate sign per timestep ---------------------------
__global__ void gate_kernel(const float* __restrict__ bias) {
    int t = blockIdx.x;
    int tid = threadIdx.x;
    float p = 0.f;
    for (int d = tid; d < D_DIM; d += 256) {
        p += g_colsum[t * D_DIM + d] * g_wcol[d] + 128.0f * bias[d];
    }
    __shared__ float red[256];
    red[tid] = p;
    __syncthreads();
    for (int s = 128; s > 0; s >>= 1) {
        if (tid < s) red[tid] += red[tid + s];
        __syncthreads();
    }
    if (tid == 0) g_sign[t] = (red[0] > 0.f) ? 1.f : -1.f;
}

// ---------------- kernel 4: Z = sign[t] * (Xr @ Wr^T + b), TF32 GEMM ---------
// CTA tile 128x128 (M tile = one timestep), 4 warps, warp tile 64x64.
// BK=32, 4 smem buffers, cp.async prefetch depth 3.
// LDS.32 per MMA = 1.0 (was 2.0 in the 32x32-warp-tile version).
#define BK      32
#define LDPAD   36                       // floats per smem row
#define STAGES  4
#define A_STG   (128 * LDPAD)            // floats per A stage
#define B_STG   (128 * LDPAD)
#define STG_FLOATS (A_STG + B_STG)
#define GEMM_SMEM_BYTES (STAGES * STG_FLOATS * 4)   // 147456

__global__ void __launch_bounds__(128, 1) gemm_kernel(const float* __restrict__ bias) {
    extern __shared__ float smem[];

    const int tid  = threadIdx.x;
    const int lane = tid & 31;
    const int warp = tid >> 5;       // 0..3
    const int wm   = warp >> 1;      // 0..1 : 64-row half
    const int wn   = warp & 1;       // 0..1 : 64-col half
    const int lr   = lane >> 2;      // 0..7
    const int lc   = lane & 3;       // 0..3

    const int bx = blockIdx.x;       // n tile (N/128 = 8)
    const int by = blockIdx.y;       // m tile = timestep t (256)

    const float* Ag = g_Xr + (size_t)by * 128 * D_DIM;
    const float* Bg = g_Wr + (size_t)bx * 128 * D_DIM;

    const int ldr = tid >> 3;        // loader row 0..15 (x8 iters -> 128 rows)
    const int ldc = tid & 7;         // loader float4 col 0..7

    float4 acc[4][8];
#pragma unroll
    for (int i = 0; i < 4; i++)
#pragma unroll
        for (int j = 0; j < 8; j++) acc[i][j] = make_float4(0.f, 0.f, 0.f, 0.f);

    auto load_stage = [&](int stg) {
        float* sA = smem + (stg & (STAGES - 1)) * STG_FLOATS;
        float* sB = sA + A_STG;
        const float* ag = Ag + stg * BK + ldc * 4;
        const float* bg = Bg + stg * BK + ldc * 4;
#pragma unroll
        for (int rr = 0; rr < 8; rr++) {
            int r = ldr + rr * 16;
            cp_async16(&sA[r * LDPAD + ldc * 4], ag + (size_t)r * D_DIM);
            cp_async16(&sB[r * LDPAD + ldc * 4], bg + (size_t)r * D_DIM);
        }
        CP_COMMIT();
    };

    load_stage(0);
    load_stage(1);
    load_stage(2);

    const int NT = D_DIM / BK;       // 32
    for (int kt = 0; kt < NT; kt++) {
        asm volatile("cp.async.wait_group 2;\n" ::: "memory");
        __syncthreads();

        if (kt + 3 < NT) load_stage(kt + 3);   // overlap loads with MMA

        const float* sA = smem + (kt & (STAGES - 1)) * STG_FLOATS;
        const float* sB = sA + A_STG;

#pragma unroll
        for (int s = 0; s < BK / 8; s++) {
            const int c0 = s * 8 + lc;
            uint32_t af[4][4];
#pragma unroll
            for (int i = 0; i < 4; i++) {
                int r0 = wm * 64 + i * 16 + lr;
                af[i][0] = __float_as_uint(sA[r0 * LDPAD + c0]);
                af[i][1] = __float_as_uint(sA[(r0 + 8) * LDPAD + c0]);
                af[i][2] = __float_as_uint(sA[r0 * LDPAD + c0 + 4]);
                af[i][3] = __float_as_uint(sA[(r0 + 8) * LDPAD + c0 + 4]);
            }
#pragma unroll
            for (int j = 0; j < 8; j++) {
                int n0 = wn * 64 + j * 8 + lr;
                uint32_t b0 = __float_as_uint(sB[n0 * LDPAD + c0]);
                uint32_t b1 = __float_as_uint(sB[n0 * LDPAD + c0 + 4]);
#pragma unroll
                for (int i = 0; i < 4; i++) mma_tf32(acc[i][j], af[i], b0, b1);
            }
        }
        __syncthreads();
    }

    // epilogue: gate sign uniform per CTA (one timestep per m-tile)
    const float sgn = g_sign[by];
#pragma unroll
    for (int i = 0; i < 4; i++) {
        int row = by * 128 + wm * 64 + i * 16 + lr;
#pragma unroll
        for (int j = 0; j < 8; j++) {
            int col = bx * 128 + wn * 64 + j * 8 + lc * 2;
            float bc0 = bias[col], bc1 = bias[col + 1];
            float2 v0 = make_float2(sgn * (acc[i][j].x + bc0), sgn * (acc[i][j].y + bc1));
            float2 v1 = make_float2(sgn * (acc[i][j].z + bc0), sgn * (acc[i][j].w + bc1));
            *reinterpret_cast<float2*>(&g_Z[(size_t)row * D_DIM + col])       = v0;
            *reinterpret_cast<float2*>(&g_Z[(size_t)(row + 8) * D_DIM + col]) = v1;
        }
    }
}

// ---------------- kernel 5: elementwise scan h = tanh(Z[t] + h) --------------
__device__ __forceinline__ float fast_tanh(float x) {
    x = fminf(fmaxf(x, -12.f), 12.f);
    float e = __expf(2.f * x);
    return __fdividef(e - 1.f, e + 1.f);
}

__global__ void scan_kernel(float* __restrict__ out, int out_size) {
    int gid = blockIdx.x * 256 + threadIdx.x;   // 0 .. BD-1
    float h = 0.f;
#pragma unroll 4
    for (int t = 0; t < T_STEPS; t++) {
        h = fast_tanh(g_Z[(size_t)t * BD + gid] + h);
    }
    out[gid] = h;
    if (out_size >= 2 * BD) out[BD + gid] = h;   // reference returns (h, h)
}

// ---------------- launch -----------------------------------------------------
extern "C" void kernel_launch(void* const* d_in, const int* in_sizes, int n_in,
                              void* d_out, int out_size) {
    const float* xs   = (const float*)d_in[0];   // [T, B, D]
    const float* W    = (const float*)d_in[1];   // [D, D]
    const float* bias = (const float*)d_in[2];   // [D]
    float* out = (float*)d_out;

    cudaFuncSetAttribute(gemm_kernel,
                         cudaFuncAttributeMaxDynamicSharedMemorySize,
                         GEMM_SMEM_BYTES);

    colsum_cvt_kernel<<<dim3(D_DIM / 256, T_STEPS), 256>>>(xs);
    wcol_cvt_kernel<<<D_DIM / 256, 256>>>(W);
    gate_kernel<<<T_STEPS, 256>>>(bias);
    gemm_kernel<<<dim3(D_DIM / 128, M_TOT / 128), 128, GEMM_SMEM_BYTES>>>(bias);
    scan_kernel<<<BD / 256, 256>>>(out, out_size);
}

// round 4
// speedup vs baseline: 1.2878x; 1.0859x over previous
#include <cuda_runtime.h>
#include <cstdint>
#include <math.h>

#define T_STEPS 256
#define B_DIM   128
#define D_DIM   1024
#define BD      (B_DIM * D_DIM)          // 131072
#define M_TOT   (T_STEPS * B_DIM)        // 32768

// ---------------- scratch (device globals; no cudaMalloc allowed) ----------
__device__ float g_Z[T_STEPS * (size_t)BD];      // gated pre-activations, 134 MB
__device__ float g_Wr[D_DIM * D_DIM];            // tf32-rounded W, 4 MB
__device__ float g_colsum[T_STEPS * D_DIM];      // sum over b of xs[t,:,d]
__device__ float g_wcol[D_DIM];                  // sum over e of W[e,d]
__device__ float g_sign[T_STEPS];                // gate sign per step

// ---------------- helpers ---------------------------------------------------
__device__ __forceinline__ float tf32_rna(float x) {
    uint32_t u;
    asm("cvt.rna.tf32.f32 %0, %1;" : "=r"(u) : "f"(x));
    return __uint_as_float(u);
}
__device__ __forceinline__ uint32_t tf32_rna_u(float x) {
    uint32_t u;
    asm("cvt.rna.tf32.f32 %0, %1;" : "=r"(u) : "f"(x));
    return u;
}

__device__ __forceinline__ void cp_async16(void* smem, const void* gmem) {
    uint32_t s = (uint32_t)__cvta_generic_to_shared(smem);
    asm volatile("cp.async.cg.shared.global [%0], [%1], 16;\n" :: "r"(s), "l"(gmem));
}
#define CP_COMMIT() asm volatile("cp.async.commit_group;\n" ::: "memory")

__device__ __forceinline__ void mma_tf32(float4& d, const uint32_t a[4],
                                         uint32_t b0, uint32_t b1) {
    asm volatile(
        "mma.sync.aligned.m16n8k8.row.col.f32.tf32.tf32.f32 "
        "{%0,%1,%2,%3}, {%4,%5,%6,%7}, {%8,%9}, {%0,%1,%2,%3};"
        : "+f"(d.x), "+f"(d.y), "+f"(d.z), "+f"(d.w)
        : "r"(a[0]), "r"(a[1]), "r"(a[2]), "r"(a[3]), "r"(b0), "r"(b1));
}

// ---------------- kernel 1: column sums of xs over b (read-only) ------------
__global__ void colsum_kernel(const float* __restrict__ xs) {
    int d = blockIdx.x * 256 + threadIdx.x;
    int t = blockIdx.y;
    const float* base = xs + (size_t)t * BD + d;
    float s = 0.f;
#pragma unroll 8
    for (int b = 0; b < B_DIM; b++) s += base[(size_t)b * D_DIM];
    g_colsum[t * D_DIM + d] = s;
}

// ---------------- kernel 2: column sums of W over e + tf32 pre-round --------
__global__ void wcol_cvt_kernel(const float* __restrict__ W) {
    int d = blockIdx.x * 256 + threadIdx.x;
    float s = 0.f;
#pragma unroll 8
    for (int e = 0; e < D_DIM; e++) {
        float v = W[(size_t)e * D_DIM + d];
        s += v;
        g_Wr[(size_t)e * D_DIM + d] = tf32_rna(v);
    }
    g_wcol[d] = s;
}

// ---------------- kernel 3: gate sign per timestep ---------------------------
__global__ void gate_kernel(const float* __restrict__ bias) {
    int t = blockIdx.x;
    int tid = threadIdx.x;
    float p = 0.f;
    for (int d = tid; d < D_DIM; d += 256) {
        p += g_colsum[t * D_DIM + d] * g_wcol[d] + 128.0f * bias[d];
    }
    __shared__ float red[256];
    red[tid] = p;
    __syncthreads();
    for (int s = 128; s > 0; s >>= 1) {
        if (tid < s) red[tid] += red[tid + s];
        __syncthreads();
    }
    if (tid == 0) g_sign[t] = (red[0] > 0.f) ? 1.f : -1.f;
}

// ---------------- kernel 4: Z = sign[t] * (rna(xs) @ Wr^T + b), TF32 GEMM ----
// CTA tile 128x128 (one timestep), 4 warps, warp tile 64x64, BK=32.
// 3 smem buffers (110.6 KB) -> 2 CTAs/SM (8 warps/SM). A is raw xs; tf32
// rounding applied in registers post-LDS (ALU pipe is idle anyway).
#define BK      32
#define LDPAD   36
#define STAGES  3
#define A_STG   (128 * LDPAD)
#define B_STG   (128 * LDPAD)
#define STG_FLOATS (A_STG + B_STG)
#define GEMM_SMEM_BYTES (STAGES * STG_FLOATS * 4)   // 110592

__global__ void __launch_bounds__(128, 2) gemm_kernel(const float* __restrict__ xs,
                                                      const float* __restrict__ bias) {
    extern __shared__ float smem[];

    const int tid  = threadIdx.x;
    const int lane = tid & 31;
    const int warp = tid >> 5;
    const int wm   = warp >> 1;
    const int wn   = warp & 1;
    const int lr   = lane >> 2;
    const int lc   = lane & 3;

    const int bx = blockIdx.x;       // n tile (8)
    const int by = blockIdx.y;       // m tile = timestep t (256)

    const float* Ag = xs   + (size_t)by * 128 * D_DIM;
    const float* Bg = g_Wr + (size_t)bx * 128 * D_DIM;

    const int ldr = tid >> 3;
    const int ldc = tid & 7;

    float4 acc[4][8];
#pragma unroll
    for (int i = 0; i < 4; i++)
#pragma unroll
        for (int j = 0; j < 8; j++) acc[i][j] = make_float4(0.f, 0.f, 0.f, 0.f);

    auto load_stage = [&](int stg) {
        float* sA = smem + (stg % STAGES) * STG_FLOATS;
        float* sB = sA + A_STG;
        const float* ag = Ag + stg * BK + ldc * 4;
        const float* bg = Bg + stg * BK + ldc * 4;
#pragma unroll
        for (int rr = 0; rr < 8; rr++) {
            int r = ldr + rr * 16;
            cp_async16(&sA[r * LDPAD + ldc * 4], ag + (size_t)r * D_DIM);
            cp_async16(&sB[r * LDPAD + ldc * 4], bg + (size_t)r * D_DIM);
        }
        CP_COMMIT();
    };

    load_stage(0);
    load_stage(1);

    const int NT = D_DIM / BK;       // 32
    for (int kt = 0; kt < NT; kt++) {
        asm volatile("cp.async.wait_group 1;\n" ::: "memory");
        __syncthreads();

        if (kt + 2 < NT) load_stage(kt + 2);

        const float* sA = smem + (kt % STAGES) * STG_FLOATS;
        const float* sB = sA + A_STG;

#pragma unroll
        for (int s = 0; s < BK / 8; s++) {
            const int c0 = s * 8 + lc;
            uint32_t af[4][4];
#pragma unroll
            for (int i = 0; i < 4; i++) {
                int r0 = wm * 64 + i * 16 + lr;
                af[i][0] = tf32_rna_u(sA[r0 * LDPAD + c0]);
                af[i][1] = tf32_rna_u(sA[(r0 + 8) * LDPAD + c0]);
                af[i][2] = tf32_rna_u(sA[r0 * LDPAD + c0 + 4]);
                af[i][3] = tf32_rna_u(sA[(r0 + 8) * LDPAD + c0 + 4]);
            }
#pragma unroll
            for (int j = 0; j < 8; j++) {
                int n0 = wn * 64 + j * 8 + lr;
                uint32_t b0 = __float_as_uint(sB[n0 * LDPAD + c0]);
                uint32_t b1 = __float_as_uint(sB[n0 * LDPAD + c0 + 4]);
#pragma unroll
                for (int i = 0; i < 4; i++) mma_tf32(acc[i][j], af[i], b0, b1);
            }
        }
        __syncthreads();
    }

    const float sgn = g_sign[by];
#pragma unroll
    for (int i = 0; i < 4; i++) {
        int row = by * 128 + wm * 64 + i * 16 + lr;
#pragma unroll
        for (int j = 0; j < 8; j++) {
            int col = bx * 128 + wn * 64 + j * 8 + lc * 2;
            float bc0 = bias[col], bc1 = bias[col + 1];
            float2 v0 = make_float2(sgn * (acc[i][j].x + bc0), sgn * (acc[i][j].y + bc1));
            float2 v1 = make_float2(sgn * (acc[i][j].z + bc0), sgn * (acc[i][j].w + bc1));
            *reinterpret_cast<float2*>(&g_Z[(size_t)row * D_DIM + col])       = v0;
            *reinterpret_cast<float2*>(&g_Z[(size_t)(row + 8) * D_DIM + col]) = v1;
        }
    }
}

// ---------------- kernel 5: elementwise scan h = tanh(Z[t] + h) --------------
__device__ __forceinline__ float fast_tanh(float x) {
    x = fminf(fmaxf(x, -12.f), 12.f);
    float e = __expf(2.f * x);
    return __fdividef(e - 1.f, e + 1.f);
}

__global__ void scan_kernel(float* __restrict__ out, int out_size) {
    int gid = blockIdx.x * 256 + threadIdx.x;
    float h = 0.f;
#pragma unroll 4
    for (int t = 0; t < T_STEPS; t++) {
        h = fast_tanh(g_Z[(size_t)t * BD + gid] + h);
    }
    out[gid] = h;
    if (out_size >= 2 * BD) out[BD + gid] = h;   // reference returns (h, h)
}

// ---------------- launch -----------------------------------------------------
extern "C" void kernel_launch(void* const* d_in, const int* in_sizes, int n_in,
                              void* d_out, int out_size) {
    const float* xs   = (const float*)d_in[0];   // [T, B, D]
    const float* W    = (const float*)d_in[1];   // [D, D]
    const float* bias = (const float*)d_in[2];   // [D]
    float* out = (float*)d_out;

    cudaFuncSetAttribute(gemm_kernel,
                         cudaFuncAttributeMaxDynamicSharedMemorySize,
                         GEMM_SMEM_BYTES);

    colsum_kernel<<<dim3(D_DIM / 256, T_STEPS), 256>>>(xs);
    wcol_cvt_kernel<<<D_DIM / 256, 256>>>(W);
    gate_kernel<<<T_STEPS, 256>>>(bias);
    gemm_kernel<<<dim3(D_DIM / 128, M_TOT / 128), 128, GEMM_SMEM_BYTES>>>(xs, bias);
    scan_kernel<<<BD / 256, 256>>>(out, out_size);
}